// round 5
// baseline (speedup 1.0000x reference)
#include <cuda_runtime.h>
#include <cstdint>

// DilateAttention: B=4, d=384 (12 heads x 32), H=W=64, 3x3 kernel, dilation 2, zero pad 2.
// q,k,v: [B, 384, 64, 64] f32. out: [B, 64, 64, 384] f32.
// Channel-split scheme: each thread owns 16 channels of one pixel; lane pairs
// (i, i+16) within a warp hold the two channel halves of the same pixel and
// combine QK partials with one shfl_xor(16).

#define NH  12
#define HD  32
#define HH  64
#define WW  64
#define TH  4
#define RR  (TH + 4)            // 8 halo rows
#define CC  68                  // 64 + 2 zero-pad each side
#define PS  (RR * CC)           // 544 floats per channel plane
// channel plane offset: +16 floats for channels >= 16 so the two half-warps
// land on disjoint bank halves (16*544 == 0 mod 32 banks otherwise)
#define SMEM_FLOATS (2 + 32 * PS + 16 + 8)
#define SCALE 0.17677669529663689f   // 32^-0.5

__device__ __forceinline__ void cp_async16(uint32_t saddr, const void* gptr) {
    asm volatile("cp.async.cg.shared.global [%0], [%1], 16;\n" :: "r"(saddr), "l"(gptr));
}
__device__ __forceinline__ void cp_commit_wait() {
    asm volatile("cp.async.commit_group;\ncp.async.wait_group 0;\n" ::: "memory");
}

__global__ __launch_bounds__(512, 2)
void dilate_attn_kernel(const float* __restrict__ q,
                        const float* __restrict__ k,
                        const float* __restrict__ v,
                        float* __restrict__ out)
{
    extern __shared__ float smem[];
    float* tile = smem + 2;   // shift so interior cp.async dst is 16B-aligned

    const int tid  = threadIdx.x;          // 0..511
    const int lane = tid & 31;
    const int wid  = tid >> 5;             // 0..15
    const int px   = wid * 16 + (lane & 15);   // 0..255 pixel in tile
    const int row  = px >> 6;              // 0..3
    const int col  = px & 63;              // 0..63
    const int ch0  = (lane & 16);          // 0 or 16: this thread's channel base

    const int h0   = blockIdx.x * TH;
    const int bh   = blockIdx.y;           // 0..47
    const int b    = bh / NH;
    const int head = bh - b * NH;
    const size_t base = ((size_t)b * 384 + (size_t)head * HD) * (HH * WW);

    // ---- stage k halo tile: threads 0..255, one (channel,row) each ----
    if (tid < 256) {
        const int sc = tid >> 3;           // channel 0..31
        const int sr = tid & 7;            // halo row 0..7
        const int gh = h0 - 2 + sr;
        const int rowbase = sc * PS + ((sc >= 16) ? 16 : 0) + sr * CC;
        if ((unsigned)gh < HH) {
            const float* gk = k + base + (size_t)sc * (HH * WW) + gh * WW;
            const uint32_t s_int =
                (uint32_t)__cvta_generic_to_shared(&tile[rowbase + 2]);
            #pragma unroll
            for (int j = 0; j < 16; j++) cp_async16(s_int + j * 16, gk + j * 4);
            tile[rowbase + 0] = 0.f;  tile[rowbase + 1] = 0.f;
            tile[rowbase + 66] = 0.f; tile[rowbase + 67] = 0.f;
        } else {
            #pragma unroll
            for (int j = 0; j < CC; j++) tile[rowbase + j] = 0.f;
        }
    }

    // ---- q (16 channels) into registers while cp.async streams ----
    const int h = h0 + row;
    float qr[16];
    {
        const float* qp = q + base + (size_t)ch0 * (HH * WW) + h * WW + col;
        #pragma unroll
        for (int c = 0; c < 16; c++) qr[c] = qp[(size_t)c * (HH * WW)];
    }

    cp_commit_wait();
    __syncthreads();                       // the only CTA barrier

    // ---- logits: 16-wide partial dot + shuffle-combine across lane pairs ----
    const int chbase = ch0 * PS + (ch0 ? 16 : 0);
    float lg[9];
    #pragma unroll
    for (int kp = 0; kp < 9; kp++) {
        const int di = kp / 3;
        const int dj = kp - di * 3;
        const float* kr = &tile[chbase + (row + 2 * di) * CC + col + 2 * dj];
        float d0 = 0.f, d1 = 0.f;
        #pragma unroll
        for (int c = 0; c < 16; c += 2) {
            d0 = fmaf(qr[c],     kr[(c)     * PS], d0);
            d1 = fmaf(qr[c + 1], kr[(c + 1) * PS], d1);
        }
        const float partial = d0 + d1;
        const float full = partial + __shfl_xor_sync(0xffffffffu, partial, 16);
        lg[kp] = full * SCALE;             // OOB neighbor: k==0 in smem -> logit 0
    }

    // ---- softmax over 9 (computed redundantly in both halves) ----
    float m = lg[0];
    #pragma unroll
    for (int kp = 1; kp < 9; kp++) m = fmaxf(m, lg[kp]);
    float p[9];
    float s = 0.f;
    #pragma unroll
    for (int kp = 0; kp < 9; kp++) { p[kp] = __expf(lg[kp] - m); s += p[kp]; }
    const float inv = __fdividef(1.f, s);

    // ---- weighted v: direct predicated LDG (L1-resident, coalesced halves) ----
    float acc[16];
    #pragma unroll
    for (int c = 0; c < 16; c++) acc[c] = 0.f;

    #pragma unroll
    for (int kp = 0; kp < 9; kp++) {
        const int di = kp / 3;
        const int dj = kp - di * 3;
        const int gh2 = h   - 2 + 2 * di;
        const int gw2 = col - 2 + 2 * dj;
        const bool ok = ((unsigned)gh2 < HH) && ((unsigned)gw2 < WW);
        const float pw = p[kp];
        const float* vp = v + base + (size_t)ch0 * (HH * WW)
                            + (ptrdiff_t)(gh2 * WW + gw2);
        #pragma unroll
        for (int c = 0; c < 16; c++) {
            const float vv = ok ? __ldg(vp + (ptrdiff_t)c * (HH * WW)) : 0.f;
            acc[c] = fmaf(pw, vv, acc[c]);
        }
    }

    // ---- contiguous 64B store per thread (4 x STG.128) ----
    const size_t obase = (((size_t)b * HH + h) * WW + col) * 384
                         + (size_t)head * HD + ch0;
    float4* o4 = (float4*)(out + obase);
    #pragma unroll
    for (int i = 0; i < 4; i++) {
        float4 t;
        t.x = acc[4 * i + 0] * inv;
        t.y = acc[4 * i + 1] * inv;
        t.z = acc[4 * i + 2] * inv;
        t.w = acc[4 * i + 3] * inv;
        o4[i] = t;
    }
}

extern "C" void kernel_launch(void* const* d_in, const int* in_sizes, int n_in,
                              void* d_out, int out_size)
{
    const float* q = (const float*)d_in[0];
    const float* k = (const float*)d_in[1];
    const float* v = (const float*)d_in[2];
    float* out = (float*)d_out;

    const int smem_bytes = SMEM_FLOATS * sizeof(float);   // ~69.8 KB
    cudaFuncSetAttribute(dilate_attn_kernel,
                         cudaFuncAttributeMaxDynamicSharedMemorySize, smem_bytes);

    dim3 block(512, 1, 1);
    dim3 grid(HH / TH, 4 * NH, 1);        // (16, 48)
    dilate_attn_kernel<<<grid, block, smem_bytes>>>(q, k, v, out);
}